// round 4
// baseline (speedup 1.0000x reference)
#include <cuda_runtime.h>
#include <math.h>

// Problem sizes (fixed)
#define BATCH  64
#define SEQ    512
#define INDIM  512
#define HID    1024
#define OUTDIM 512

// RNN partitioning: 4 batch-groups x 32 h-slices = 128 persistent CTAs
#define RGROUPS 4
#define RBPG    16
#define RSLICES 32
#define RHS     32

// ---------------------------------------------------------------------------
// Scratch (static device arrays; no allocation allowed)
// ---------------------------------------------------------------------------
__device__ float g_xu[BATCH * SEQ * HID];        // 128 MB
__device__ float g_s[3][BATCH * HID];            // triple-buffered state
__device__ unsigned g_flags[RGROUPS * RSLICES * 32];  // per-slice flags, 128B apart

// ---------------------------------------------------------------------------
// Packed fp32x2 FMA (Blackwell FFMA2; only reachable via PTX fma.rn.f32x2)
// ---------------------------------------------------------------------------
union F2U { float2 f; unsigned long long u; };
__device__ __forceinline__ float2 ffma2(float2 a, float2 b, float2 c) {
    F2U A, B, C, D;
    A.f = a; B.f = b; C.f = c;
    asm("fma.rn.f32x2 %0, %1, %2, %3;" : "=l"(D.u) : "l"(A.u), "l"(B.u), "l"(C.u));
    return D.f;
}

__device__ __forceinline__ unsigned ld_acq(const unsigned* p) {
    unsigned v;
    asm volatile("ld.acquire.gpu.global.u32 %0, [%1];" : "=r"(v) : "l"(p) : "memory");
    return v;
}
__device__ __forceinline__ void st_rel(unsigned* p, unsigned v) {
    asm volatile("st.release.gpu.global.u32 [%0], %1;" :: "l"(p), "r"(v) : "memory");
}

__device__ __forceinline__ float accurate_tanh(float y) {
    float ay = fabsf(y);
    float e = __expf(-2.0f * ay);
    float r = (1.0f - e) / (1.0f + e);
    return copysignf(r, y);
}

// ---------------------------------------------------------------------------
// Big GEMM: C = A * B^T + bias.  A[M][K], B[N][K] row-major (K contiguous).
// BM=64, BN=128, BK=16, 256 threads, thread tile 4m x 8n, DOUBLE-BUFFERED
// smem (one __syncthreads per k-iter; LDG prefetch overlaps compute).
// ---------------------------------------------------------------------------
__device__ __forceinline__ int posB(int n) {
    return (((n & 7) >> 1) << 5) + ((n >> 3) << 1) + (n & 1);
}

__global__ __launch_bounds__(256, 2) void gemm_nt_big(
    const float* __restrict__ A, const float* __restrict__ B,
    const float* __restrict__ bias, float* __restrict__ C, int K, int N)
{
    __shared__ __align__(16) float2 As[2][8 * 66];
    __shared__ __align__(16) float2 Bs[2][8 * 130];

    const int tid = threadIdx.x;
    const int m0 = blockIdx.y * 64, n0 = blockIdx.x * 128;
    const int mp = tid >> 4, np = tid & 15;

    const int lmA = tid >> 2, lkA = tid & 3;
    const int lnB0 = tid >> 2;
    const int lnB1 = 64 + (tid >> 2);
    const int pB0 = posB(lnB0), pB1 = posB(lnB1);

    const float* Ab  = &A[(m0 + lmA) * K + 4 * lkA];
    const float* B0b = &B[(n0 + lnB0) * K + 4 * lkA];
    const float* B1b = &B[(n0 + lnB1) * K + 4 * lkA];

    float2 acc[4][8];
    #pragma unroll
    for (int i = 0; i < 4; ++i)
        #pragma unroll
        for (int j = 0; j < 8; ++j) acc[i][j] = make_float2(0.f, 0.f);

    // prologue: fetch k-chunk 0 and stage into buffer 0
    float4 va  = *(const float4*)(Ab);
    float4 vb0 = *(const float4*)(B0b);
    float4 vb1 = *(const float4*)(B1b);
    As[0][(2 * lkA) * 66 + lmA]       = make_float2(va.x, va.y);
    As[0][(2 * lkA + 1) * 66 + lmA]   = make_float2(va.z, va.w);
    Bs[0][(2 * lkA) * 130 + pB0]      = make_float2(vb0.x, vb0.y);
    Bs[0][(2 * lkA + 1) * 130 + pB0]  = make_float2(vb0.z, vb0.w);
    Bs[0][(2 * lkA) * 130 + pB1]      = make_float2(vb1.x, vb1.y);
    Bs[0][(2 * lkA + 1) * 130 + pB1]  = make_float2(vb1.z, vb1.w);
    __syncthreads();

    int buf = 0;
    for (int kc = 0; kc < K; kc += 16) {
        const bool has_next = (kc + 16) < K;
        if (has_next) {
            va  = *(const float4*)(Ab  + kc + 16);
            vb0 = *(const float4*)(B0b + kc + 16);
            vb1 = *(const float4*)(B1b + kc + 16);
        }
        const float2* Ac = As[buf];
        const float2* Bc = Bs[buf];
        #pragma unroll
        for (int k2 = 0; k2 < 8; ++k2) {
            float4 a4a = *(const float4*)&Ac[k2 * 66 + mp * 4];
            float4 a4b = *(const float4*)&Ac[k2 * 66 + mp * 4 + 2];
            float2 sv[4] = { {a4a.x, a4a.y}, {a4a.z, a4a.w},
                             {a4b.x, a4b.y}, {a4b.z, a4b.w} };
            float2 wv[8];
            #pragma unroll
            for (int j = 0; j < 4; ++j) {
                float4 b4 = *(const float4*)&Bc[k2 * 130 + j * 32 + np * 2];
                wv[2 * j]     = make_float2(b4.x, b4.y);
                wv[2 * j + 1] = make_float2(b4.z, b4.w);
            }
            #pragma unroll
            for (int mi = 0; mi < 4; ++mi)
                #pragma unroll
                for (int ni = 0; ni < 8; ++ni)
                    acc[mi][ni] = ffma2(sv[mi], wv[ni], acc[mi][ni]);
        }
        if (has_next) {
            int nb2 = buf ^ 1;
            As[nb2][(2 * lkA) * 66 + lmA]      = make_float2(va.x, va.y);
            As[nb2][(2 * lkA + 1) * 66 + lmA]  = make_float2(va.z, va.w);
            Bs[nb2][(2 * lkA) * 130 + pB0]     = make_float2(vb0.x, vb0.y);
            Bs[nb2][(2 * lkA + 1) * 130 + pB0] = make_float2(vb0.z, vb0.w);
            Bs[nb2][(2 * lkA) * 130 + pB1]     = make_float2(vb1.x, vb1.y);
            Bs[nb2][(2 * lkA + 1) * 130 + pB1] = make_float2(vb1.z, vb1.w);
            __syncthreads();
            buf = nb2;
        }
    }

    const int nb = n0 + np * 8;
    float4 bv0 = *(const float4*)&bias[nb];
    float4 bv1 = *(const float4*)&bias[nb + 4];
    #pragma unroll
    for (int mi = 0; mi < 4; ++mi) {
        float4 o0, o1;
        o0.x = acc[mi][0].x + acc[mi][0].y + bv0.x;
        o0.y = acc[mi][1].x + acc[mi][1].y + bv0.y;
        o0.z = acc[mi][2].x + acc[mi][2].y + bv0.z;
        o0.w = acc[mi][3].x + acc[mi][3].y + bv0.w;
        o1.x = acc[mi][4].x + acc[mi][4].y + bv1.x;
        o1.y = acc[mi][5].x + acc[mi][5].y + bv1.y;
        o1.z = acc[mi][6].x + acc[mi][6].y + bv1.z;
        o1.w = acc[mi][7].x + acc[mi][7].y + bv1.w;
        float* cp = &C[(m0 + mp * 4 + mi) * N + nb];
        *(float4*)cp = o0;
        *(float4*)(cp + 4) = o1;
    }
}

// ---------------------------------------------------------------------------
// Small GEMM (epilogue, ~30us): 32x32 tile, N = gridDim.x*32.
// ---------------------------------------------------------------------------
__global__ __launch_bounds__(256) void gemm_nt_small(
    const float* __restrict__ A, const float* __restrict__ B,
    const float* __restrict__ bias, float* __restrict__ C, int K)
{
    __shared__ __align__(16) float2 As[32 * 34];
    __shared__ __align__(16) float2 Bs[32 * 34];

    const int tid = threadIdx.x;
    const int m0 = blockIdx.y * 32, n0 = blockIdx.x * 32;
    const int mp = tid >> 4, np = tid & 15;
    const int lm1 = tid >> 4, lk1 = tid & 15;
    const int lm2 = (tid + 256) >> 4, lk2 = tid & 15;

    float2 a00 = {0.f, 0.f}, a01 = {0.f, 0.f}, a10 = {0.f, 0.f}, a11 = {0.f, 0.f};

    for (int kc = 0; kc < K; kc += 64) {
        float4 va1 = *(const float4*)&A[(m0 + lm1) * K + kc + 4 * lk1];
        float4 va2 = *(const float4*)&A[(m0 + lm2) * K + kc + 4 * lk2];
        float4 vb1 = *(const float4*)&B[(n0 + lm1) * K + kc + 4 * lk1];
        float4 vb2 = *(const float4*)&B[(n0 + lm2) * K + kc + 4 * lk2];
        __syncthreads();
        As[(2 * lk1) * 34 + lm1]     = make_float2(va1.x, va1.y);
        As[(2 * lk1 + 1) * 34 + lm1] = make_float2(va1.z, va1.w);
        As[(2 * lk2) * 34 + lm2]     = make_float2(va2.x, va2.y);
        As[(2 * lk2 + 1) * 34 + lm2] = make_float2(va2.z, va2.w);
        Bs[(2 * lk1) * 34 + lm1]     = make_float2(vb1.x, vb1.y);
        Bs[(2 * lk1 + 1) * 34 + lm1] = make_float2(vb1.z, vb1.w);
        Bs[(2 * lk2) * 34 + lm2]     = make_float2(vb2.x, vb2.y);
        Bs[(2 * lk2 + 1) * 34 + lm2] = make_float2(vb2.z, vb2.w);
        __syncthreads();
        #pragma unroll
        for (int k2 = 0; k2 < 32; ++k2) {
            float4 xa = *(const float4*)&As[k2 * 34 + 2 * mp];
            float4 wb = *(const float4*)&Bs[k2 * 34 + 2 * np];
            float2 xl = {xa.x, xa.y}, xh = {xa.z, xa.w};
            float2 wl = {wb.x, wb.y}, wh = {wb.z, wb.w};
            a00 = ffma2(xl, wl, a00);
            a01 = ffma2(xl, wh, a01);
            a10 = ffma2(xh, wl, a10);
            a11 = ffma2(xh, wh, a11);
        }
    }

    const int N = gridDim.x * 32;
    const int m = m0 + 2 * mp, n = n0 + 2 * np;
    const float b0v = bias[n], b1v = bias[n + 1];
    C[m * N + n]           = a00.x + a00.y + b0v;
    C[m * N + n + 1]       = a01.x + a01.y + b1v;
    C[(m + 1) * N + n]     = a10.x + a10.y + b0v;
    C[(m + 1) * N + n + 1] = a11.x + a11.y + b1v;
}

// ---------------------------------------------------------------------------
// Init: zero state buffer 0 + all flags (every replay, determinism)
// ---------------------------------------------------------------------------
__global__ void init_kernel()
{
    int i = blockIdx.x * blockDim.x + threadIdx.x;
    int nth = gridDim.x * blockDim.x;
    for (int j = i; j < BATCH * HID; j += nth) g_s[0][j] = 0.0f;
    for (int j = i; j < RGROUPS * RSLICES * 32; j += nth) g_flags[j] = 0u;
}

// ---------------------------------------------------------------------------
// Persistent recurrence kernel — warp-autonomous pipeline.
// 128 CTAs (4 groups x 32 slices), 256 threads, 1 CTA/SM.
// Warp kg handles k in [128kg,128kg+128) = state slices 4kg..4kg+3:
//   poll 4 flags (acquire) -> stage own 8KB (cg) -> compute 4b x 4h f32x2
//   -> write partials P[kg] -> syncthreads -> reduce+tanh+STG state
//   -> syncthreads -> tid0 st.release flag.
// Triple-buffered state removes the WAR race without acks (see analysis).
// Smem: Wws[kg][i][h] stride 34 f2 (rows 16B-aligned);
//       Ss[kg][i][b] stride 18 f2;  P[kg][o] stride 520 f.
// ---------------------------------------------------------------------------
#define WW_BYTES (8 * 64 * 34 * 8)             // 139264
#define SS_OFF   WW_BYTES
#define SS_BYTES (8 * 64 * 18 * 8)             // 73728
#define P_OFF    (SS_OFF + SS_BYTES)           // 212992
#define P_BYTES  (8 * 520 * 4)                 // 16640
#define RNN_SMEM (P_OFF + P_BYTES)             // 229632 (<= 232448)

__global__ __launch_bounds__(256, 1) void rnn_step_kernel(
    const float* __restrict__ Ww, const float* __restrict__ bw)
{
    extern __shared__ __align__(16) char smem[];
    float2* Wws = (float2*)smem;
    float2* Ss  = (float2*)(smem + SS_OFF);
    float*  P   = (float*)(smem + P_OFF);

    const int tid   = threadIdx.x;
    const int g     = blockIdx.x >> 5;
    const int slice = blockIdx.x & 31;
    const int h0    = slice * RHS;
    const int b0    = g * RBPG;

    // One-time: Ww slice [32h x 1024k] -> [kg][i][h], stride 34 f2
    for (int idx = tid; idx < RHS * 256; idx += 256) {
        int h = idx >> 8, j = idx & 255;          // j: float4 index over k
        float4 v = *(const float4*)&Ww[(h0 + h) * HID + 4 * j];
        int kg = j >> 5;
        int i  = 2 * (j & 31);
        Wws[(kg * 64 + i) * 34 + h]     = make_float2(v.x, v.y);
        Wws[(kg * 64 + i + 1) * 34 + h] = make_float2(v.z, v.w);
    }

    const int kg = tid >> 5, lid = tid & 31;
    const int hg = (lid >> 2) & 7, bg = lid & 3;
    const float2* sBase = Ss  + (kg * 64) * 18 + bg * 4;
    const float2* wBase = Wws + (kg * 64) * 34 + hg * 4;
    float* P_my = P + kg * 520;

    // staging coords: lane covers (batch st_b, column-half st_jh)
    const int st_b = lid & 15, st_jh = lid >> 4;
    float2* stDst = Ss + (kg * 64 + 32 * st_jh) * 18 + st_b;

    // flags
    unsigned* myflag = &g_flags[(g * 32 + slice) * 32];
    const unsigned* pollflag =
        &g_flags[(g * 32 + (kg * 4 + (lid & 3))) * 32];

    // finalize coords: thread handles outputs o = 2*tid, 2*tid+1
    const int fb = tid >> 4;
    const int fh = (tid & 15) * 2;
    const float2 bwv = *(const float2*)&bw[h0 + fh];
    const float* xup = &g_xu[(size_t)(b0 + fb) * SEQ * HID + h0 + fh];
    float* soutBase = &g_s[0][(b0 + fb) * HID + h0 + fh];

    __syncthreads();   // Wws visible to all warps

    int cur = 0, nxt = 1;
    for (int t = 0; t < SEQ; ++t) {
        // prefetch xu for this step (consumed after sync_A)
        const float2 xv = __ldcg((const float2*)(xup + (size_t)t * HID));

        // warp-local: poll the 4 producer flags for this k-range
        if (lid < 4) {
            unsigned v;
            do {
                v = ld_acq(pollflag);
            } while ((int)v < t);
        }
        __syncwarp();

        // stage own 8KB: s[b][128k of kg] -> Ss[kg][i][b]
        {
            const float* sc =
                &g_s[cur][(b0 + st_b) * HID + kg * 128 + st_jh * 64];
            #pragma unroll
            for (int q = 0; q < 16; ++q) {
                float4 v = __ldcg((const float4*)(sc + 4 * q));
                stDst[(2 * q) * 18]     = make_float2(v.x, v.y);
                stDst[(2 * q + 1) * 18] = make_float2(v.z, v.w);
            }
        }
        __syncwarp();

        // compute 4b x 4h over this kg's 64 k-pairs
        float2 acc[4][4];
        #pragma unroll
        for (int c = 0; c < 4; ++c)
            #pragma unroll
            for (int hh = 0; hh < 4; ++hh) acc[c][hh] = make_float2(0.f, 0.f);

        #pragma unroll 4
        for (int i = 0; i < 64; ++i) {
            float4 s4a = *(const float4*)(sBase + i * 18);
            float4 s4b = *(const float4*)(sBase + i * 18 + 2);
            float4 w4a = *(const float4*)(wBase + i * 34);
            float4 w4b = *(const float4*)(wBase + i * 34 + 2);
            float2 sv[4] = { {s4a.x, s4a.y}, {s4a.z, s4a.w},
                             {s4b.x, s4b.y}, {s4b.z, s4b.w} };
            float2 wv[4] = { {w4a.x, w4a.y}, {w4a.z, w4a.w},
                             {w4b.x, w4b.y}, {w4b.z, w4b.w} };
            #pragma unroll
            for (int c = 0; c < 4; ++c)
                #pragma unroll
                for (int hh = 0; hh < 4; ++hh)
                    acc[c][hh] = ffma2(sv[c], wv[hh], acc[c][hh]);
        }

        // partials: P[kg][o], o = (bg*4+c)*32 + hg*4 .. +3  (one STS.128 per c)
        #pragma unroll
        for (int c = 0; c < 4; ++c) {
            float4 pv;
            pv.x = acc[c][0].x + acc[c][0].y;
            pv.y = acc[c][1].x + acc[c][1].y;
            pv.z = acc[c][2].x + acc[c][2].y;
            pv.w = acc[c][3].x + acc[c][3].y;
            *(float4*)&P_my[(bg * 4 + c) * 32 + hg * 4] = pv;
        }
        __syncthreads();   // sync_A: all partials visible

        // reduce over 8 kg + xu + bias, tanh, write next state
        float2 y = make_float2(xv.x + bwv.x, xv.y + bwv.y);
        #pragma unroll
        for (int k = 0; k < 8; ++k) {
            float2 p = *(const float2*)&P[k * 520 + 2 * tid];
            y.x += p.x; y.y += p.y;
        }
        float2 sn = make_float2(accurate_tanh(y.x), accurate_tanh(y.y));
        *(float2*)(soutBase + (size_t)nxt * BATCH * HID) = sn;

        __syncthreads();   // sync_B: all state STGs ordered before release
        if (tid == 0) st_rel(myflag, (unsigned)(t + 1));

        cur = nxt;
        nxt = (nxt == 2) ? 0 : nxt + 1;
    }
}

// ---------------------------------------------------------------------------
// kernel_launch
// ---------------------------------------------------------------------------
extern "C" void kernel_launch(void* const* d_in, const int* in_sizes, int n_in,
                              void* d_out, int out_size)
{
    const float* x  = (const float*)d_in[0];
    const float* Wu = (const float*)d_in[1];
    const float* bu = (const float*)d_in[2];
    const float* Ww = (const float*)d_in[3];
    const float* bw = (const float*)d_in[4];
    const float* Wv = (const float*)d_in[5];
    const float* bv = (const float*)d_in[6];
    float* out = (float*)d_out;
    (void)in_sizes; (void)n_in; (void)out_size;

    static bool attr_set = false;
    if (!attr_set) {
        cudaFuncSetAttribute(rnn_step_kernel,
                             cudaFuncAttributeMaxDynamicSharedMemorySize, RNN_SMEM);
        attr_set = true;
    }

    void* xu_ptr = nullptr;
    void* s_ptr  = nullptr;
    cudaGetSymbolAddress(&xu_ptr, g_xu);
    cudaGetSymbolAddress(&s_ptr, g_s);
    // final state: step t writes buffer (t+1)%3 -> t=511 writes buffer 2
    const float* s_final = (const float*)s_ptr + 2 * BATCH * HID;

    // 0) reset state buffer 0 + flags (every replay)
    init_kernel<<<64, 256>>>();

    // 1) xu = x @ Wu^T + bu   (M=32768, N=1024, K=512)
    gemm_nt_big<<<dim3(HID / 128, (BATCH * SEQ) / 64), 256>>>(
        x, Wu, bu, (float*)xu_ptr, INDIM, HID);

    // 2) recurrence (persistent, 128 co-resident CTAs)
    rnn_step_kernel<<<RGROUPS * RSLICES, 256, RNN_SMEM>>>(Ww, bw);

    // 3) out = s_final @ Wv^T + bv   (M=64, N=512, K=1024)
    gemm_nt_small<<<dim3(OUTDIM / 32, BATCH / 32), 256>>>(
        s_final, Wv, bv, out, HID);
}